// round 3
// baseline (speedup 1.0000x reference)
#include <cuda_runtime.h>

// out = kipf - lbda[row] * input
// input, kipf: [100000, 256] fp32; lbda: [100000] fp32
// R1 structure (1 float4/thread, max resident warps) + evict-first loads on
// the two dead streams. Stores and lbda use default caching.

__global__ __launch_bounds__(256) void damping_kernel(
    const float4* __restrict__ input4,
    const float4* __restrict__ kipf4,
    const float*  __restrict__ lbda,
    float4* __restrict__ out4,
    int n4)  // total float4 count
{
    int i = blockIdx.x * blockDim.x + threadIdx.x;
    if (i >= n4) return;

    int row = i >> 6;               // 64 float4 per 256-float row
    float l = __ldg(&lbda[row]);    // broadcast; reused -> keep cached

    float4 a = __ldcs(input4 + i);  // streaming: dead after use
    float4 k = __ldcs(kipf4  + i);  // streaming: dead after use

    float4 r;
    r.x = fmaf(-l, a.x, k.x);
    r.y = fmaf(-l, a.y, k.y);
    r.z = fmaf(-l, a.z, k.z);
    r.w = fmaf(-l, a.w, k.w);

    out4[i] = r;
}

extern "C" void kernel_launch(void* const* d_in, const int* in_sizes, int n_in,
                              void* d_out, int out_size) {
    const float4* input4 = (const float4*)d_in[0];   // input_term
    const float4* kipf4  = (const float4*)d_in[1];   // kipf_term
    const float*  lbda   = (const float*)d_in[2];    // lbda
    // d_in[3] = spar (unused, always 1)

    int n  = out_size;        // 25,600,000
    int n4 = n / 4;           // 6,400,000

    int threads = 256;
    int blocks  = (n4 + threads - 1) / threads;  // 25000
    damping_kernel<<<blocks, threads>>>(input4, kipf4, lbda, (float4*)d_out, n4);
}

// round 4
// speedup vs baseline: 1.0045x; 1.0045x over previous
#include <cuda_runtime.h>

// out = kipf - lbda[row] * input
// input, kipf: [100000, 256] fp32; lbda: [100000] fp32
// 1 float4/thread (max warp-level latency hiding), evict-first loads on the
// two dead streams, 512-thread blocks to halve block-scheduling events.

__global__ __launch_bounds__(512) void damping_kernel(
    const float4* __restrict__ input4,
    const float4* __restrict__ kipf4,
    const float*  __restrict__ lbda,
    float4* __restrict__ out4,
    int n4)  // total float4 count
{
    int i = blockIdx.x * blockDim.x + threadIdx.x;
    if (i >= n4) return;

    int row = i >> 6;               // 64 float4 per 256-float row
    float l = __ldg(&lbda[row]);    // broadcast; reused -> keep cached

    float4 a = __ldcs(input4 + i);  // streaming: dead after first use
    float4 k = __ldcs(kipf4  + i);  // streaming: dead after first use

    float4 r;
    r.x = fmaf(-l, a.x, k.x);
    r.y = fmaf(-l, a.y, k.y);
    r.z = fmaf(-l, a.z, k.z);
    r.w = fmaf(-l, a.w, k.w);

    out4[i] = r;
}

extern "C" void kernel_launch(void* const* d_in, const int* in_sizes, int n_in,
                              void* d_out, int out_size) {
    const float4* input4 = (const float4*)d_in[0];   // input_term
    const float4* kipf4  = (const float4*)d_in[1];   // kipf_term
    const float*  lbda   = (const float*)d_in[2];    // lbda
    // d_in[3] = spar (unused, always 1)

    int n  = out_size;        // 25,600,000
    int n4 = n / 4;           // 6,400,000

    int threads = 512;
    int blocks  = (n4 + threads - 1) / threads;  // 12500
    damping_kernel<<<blocks, threads>>>(input4, kipf4, lbda, (float4*)d_out, n4);
}